// round 2
// baseline (speedup 1.0000x reference)
#include <cuda_runtime.h>
#include <cuda_bf16.h>

// VQ layer forward: quantized = closest + stop_gradient(inputs - closest)
// == inputs in the forward pass (rel_err ~1e-8 vs reference, gate is 1e-3).
// So the optimal kernel is a DRAM/L2-roofline copy of d_in[0] -> d_out.
//
// R1 evidence: 1 float4/thread, 2048 CTAs => latency-bound (MLP=1, CTA churn),
// only 1.4 TB/s. Fix: 4 front-batched float4 per thread, single CTA wave.
// 512 blocks x 256 threads x 4 vec = 524,288 float4 = 8 MiB exactly.

__global__ void vq_identity_copy4(const float4* __restrict__ src,
                                  float4* __restrict__ dst,
                                  int n4) {
    const int nthreads = gridDim.x * blockDim.x;
    int i = blockIdx.x * blockDim.x + threadIdx.x;

    // Main path: exactly 4 vectors per thread, front-batched loads (MLP=4).
    int i0 = i;
    int i1 = i + nthreads;
    int i2 = i + 2 * nthreads;
    int i3 = i + 3 * nthreads;

    if (i3 < n4) {
        float4 v0 = src[i0];
        float4 v1 = src[i1];
        float4 v2 = src[i2];
        float4 v3 = src[i3];
        dst[i0] = v0;
        dst[i1] = v1;
        dst[i2] = v2;
        dst[i3] = v3;
    } else {
        // Tail (not taken for the fixed 8 MiB shape, kept for safety).
        for (int j = i0; j < n4; j += nthreads) {
            dst[j] = src[j];
        }
    }
}

extern "C" void kernel_launch(void* const* d_in, const int* in_sizes, int n_in,
                              void* d_out, int out_size) {
    const float* inputs = (const float*)d_in[0];
    float* out = (float*)d_out;

    int n4 = out_size >> 2;      // 524,288 float4

    const int threads = 256;
    const int vec_per_thread = 4;
    int blocks = (n4 + threads * vec_per_thread - 1) / (threads * vec_per_thread); // 512

    vq_identity_copy4<<<blocks, threads>>>(
        (const float4*)inputs, (float4*)out, n4);
}

// round 3
// speedup vs baseline: 1.0962x; 1.0962x over previous
#include <cuda_runtime.h>
#include <cstdint>

// VQ layer forward == identity on inputs (verified: rel_err 1.1e-8 in R1/R2).
// R1/R2 post-mortem: LDG/STG copies hit a ~6us latency floor with every pipe
// idle (DRAM 17%, L2 15%, issue <30%) regardless of occupancy/MLP shape.
// R3: route the copy through TMA bulk (cp.async.bulk), GMEM->SMEM->GMEM via
// the async proxy. 512 CTAs x 16KB chunks, all co-resident in one wave; each
// CTA: one bulk load (mbarrier completion), one bulk store (bulk_group).

#define CHUNK 16384

__device__ __forceinline__ uint32_t smem_u32(const void* p) {
    uint32_t a;
    asm("{ .reg .u64 t; cvta.to.shared.u64 t, %1; cvt.u32.u64 %0, t; }"
        : "=r"(a) : "l"(p));
    return a;
}

__global__ void __launch_bounds__(32, 1) vq_tma_copy(const char* __restrict__ src,
                                                     char* __restrict__ dst) {
    __shared__ alignas(128) char buf[CHUNK];
    __shared__ alignas(8) uint64_t mbar;

    if (threadIdx.x == 0) {
        const uint32_t mbar_a = smem_u32(&mbar);
        const uint32_t buf_a  = smem_u32(buf);
        const size_t off = (size_t)blockIdx.x * CHUNK;

        // Init mbarrier, make it visible to the async proxy.
        asm volatile("mbarrier.init.shared.b64 [%0], 1;" :: "r"(mbar_a) : "memory");
        asm volatile("fence.proxy.async.shared::cta;" ::: "memory");

        // Bulk load: global -> shared, completion via mbarrier tx bytes.
        asm volatile("mbarrier.arrive.expect_tx.shared.b64 _, [%0], %1;"
                     :: "r"(mbar_a), "r"((uint32_t)CHUNK) : "memory");
        asm volatile(
            "cp.async.bulk.shared::cta.global.mbarrier::complete_tx::bytes "
            "[%0], [%1], %2, [%3];"
            :: "r"(buf_a), "l"(src + off), "r"((uint32_t)CHUNK), "r"(mbar_a)
            : "memory");

        // Wait for the load (phase parity 0).
        uint32_t done = 0;
        while (!done) {
            asm volatile(
                "{ .reg .pred p; "
                "mbarrier.try_wait.parity.shared.b64 p, [%1], 0, 10000000; "
                "selp.b32 %0, 1, 0, p; }"
                : "=r"(done) : "r"(mbar_a) : "memory");
        }

        // Bulk store: shared -> global.
        asm volatile(
            "cp.async.bulk.global.shared::cta.bulk_group [%0], [%1], %2;"
            :: "l"(dst + off), "r"(buf_a), "r"((uint32_t)CHUNK)
            : "memory");
        asm volatile("cp.async.bulk.commit_group;" ::: "memory");
        // Must drain before CTA exit (SMEM is deallocated at exit).
        asm volatile("cp.async.bulk.wait_group 0;" ::: "memory");
    }
}

extern "C" void kernel_launch(void* const* d_in, const int* in_sizes, int n_in,
                              void* d_out, int out_size) {
    const char* src = (const char*)d_in[0];
    char* dst = (char*)d_out;

    const size_t bytes = (size_t)out_size * sizeof(float);  // 8 MiB
    const int blocks = (int)(bytes / CHUNK);                // 512

    vq_tma_copy<<<blocks, 32>>>(src, dst);
}

// round 4
// speedup vs baseline: 1.1014x; 1.0048x over previous
#include <cuda_runtime.h>

// VQ layer forward == identity on inputs (verified rel_err 1.1e-8, gate 1e-3):
// quantized = closest + stop_gradient(inputs - closest) == inputs in fp.
//
// R1-R3 post-mortem: three different SM-side copy paths (scalar LDG/STG,
// MLP-4 batched, TMA bulk) all land at 6.1+/-0.15us with every pipe idle
// (DRAM 17%, L2 15%, issue <=30%). Duration invariant to implementation =>
// the floor is outside the SM datapath (likely DVFS clock state / grid
// ramp for ~6us kernels). R4: bypass SMs entirely -- a device-to-device
// cudaMemcpyAsync becomes a copy-engine node in the captured graph (the
// harness explicitly allows async D2D memcpy). No SM ramp, no SM clocks.

extern "C" void kernel_launch(void* const* d_in, const int* in_sizes, int n_in,
                              void* d_out, int out_size) {
    const void* src = d_in[0];
    const size_t bytes = (size_t)out_size * sizeof(float);  // 8 MiB

    cudaMemcpyAsync(d_out, src, bytes, cudaMemcpyDeviceToDevice, 0);
}